// round 5
// baseline (speedup 1.0000x reference)
#include <cuda_runtime.h>
#include <math.h>

// Problem constants
#define BATCH 8
#define HEADS 8
#define SEQ   1024
#define DM    512
#define DEPTH 64
#define MROWS (BATCH*SEQ)          // 8192
#define OUT_OFF (BATCH*SEQ*DM)     // 4194304 floats: out region, then attn region

// Scratch (device globals; no runtime allocation allowed)
__device__ float g_q [BATCH*HEADS*SEQ*DEPTH];   // [bh][s][d]
__device__ float g_kt[BATCH*HEADS*DEPTH*SEQ];   // [bh][d][s]
__device__ float g_v [BATCH*HEADS*SEQ*DEPTH];   // [bh][s][d]
__device__ float g_x [BATCH*SEQ*DM];            // [b*s][h*64+d]

// ---------------------------------------------------------------------------
// Projection / output GEMM: C[8192,512] = X[8192,512] @ W[512,512] + bias
// mode 0 -> g_q  ([bh][s][d]);  mode 1 -> g_kt ([bh][d][s]);
// mode 2 -> g_v  ([bh][s][d]);  mode 3 -> reads g_x (device symbol), writes out
// 128x128 block tile, BK=16, 256 threads, 8x8 per-thread microtile.
// ---------------------------------------------------------------------------
__global__ __launch_bounds__(256) void proj_gemm(
    const float* __restrict__ Xarg, const float* __restrict__ W,
    const float* __restrict__ bias, float* __restrict__ out, int mode)
{
    __shared__ float As[16][132];   // k-major, padded
    __shared__ float Bs[16][128];

    // CRITICAL: __device__ globals cannot be passed as kernel args from host
    // code (host-side symbol != device address). Resolve device-side instead.
    const float* X = (mode == 3) ? (const float*)g_x : Xarg;

    const int tid = threadIdx.x;
    const int tx = tid & 15, ty = tid >> 4;
    const int rowBase = blockIdx.y * 128;
    const int colBase = blockIdx.x * 128;

    float acc[8][8];
    #pragma unroll
    for (int i = 0; i < 8; i++)
        #pragma unroll
        for (int j = 0; j < 8; j++) acc[i][j] = 0.f;

    for (int k0 = 0; k0 < DM; k0 += 16) {
        // A tile: 128 rows x 16 k  (512 float4, 2 per thread)
        #pragma unroll
        for (int i = 0; i < 2; i++) {
            int idx = tid * 2 + i;            // 0..511
            int r   = idx >> 2;               // 0..127
            int c4  = idx & 3;                // 0..3
            float4 v = *(const float4*)&X[(size_t)(rowBase + r) * DM + k0 + c4 * 4];
            As[c4*4+0][r] = v.x;
            As[c4*4+1][r] = v.y;
            As[c4*4+2][r] = v.z;
            As[c4*4+3][r] = v.w;
        }
        // B tile: 16 k x 128 cols (512 float4, 2 per thread)
        #pragma unroll
        for (int i = 0; i < 2; i++) {
            int idx = tid * 2 + i;
            int kk  = idx >> 5;               // 0..15
            int c4  = idx & 31;               // 0..31
            *(float4*)&Bs[kk][c4*4] =
                *(const float4*)&W[(size_t)(k0 + kk) * DM + colBase + c4 * 4];
        }
        __syncthreads();

        #pragma unroll
        for (int kk = 0; kk < 16; kk++) {
            float a[8], b[8];
            *(float4*)&a[0] = *(const float4*)&As[kk][ty*8];
            *(float4*)&a[4] = *(const float4*)&As[kk][ty*8+4];
            *(float4*)&b[0] = *(const float4*)&Bs[kk][tx*8];
            *(float4*)&b[4] = *(const float4*)&Bs[kk][tx*8+4];
            #pragma unroll
            for (int i = 0; i < 8; i++)
                #pragma unroll
                for (int j = 0; j < 8; j++)
                    acc[i][j] = fmaf(a[i], b[j], acc[i][j]);
        }
        __syncthreads();
    }

    // Store with layout dispatch
    #pragma unroll
    for (int i = 0; i < 8; i++) {
        int m  = rowBase + ty * 8 + i;        // global row: b*1024+s
        int bb = m >> 10, s = m & 1023;
        #pragma unroll
        for (int j = 0; j < 8; j++) {
            int n = colBase + tx * 8 + j;     // global col: h*64+d
            float v = acc[i][j] + bias[n];
            int h = n >> 6, d = n & 63;
            int bh = bb * HEADS + h;
            if      (mode == 0) g_q [((size_t)bh * SEQ + s) * DEPTH + d] = v;
            else if (mode == 1) g_kt[((size_t)bh * DEPTH + d) * SEQ + s] = v;
            else if (mode == 2) g_v [((size_t)bh * SEQ + s) * DEPTH + d] = v;
            else                out[(size_t)m * DM + n] = v;
        }
    }
}

// ---------------------------------------------------------------------------
// Fused attention: scores -> softmax -> *mask/additional_weights -> attn out
// and x = attn @ V.  One block = 8 query rows of one (b,h). 256 threads.
// ---------------------------------------------------------------------------
#define AWARPS 8
__global__ __launch_bounds__(256) void attn_kernel(
    const float* __restrict__ mask,      // [B, S]
    const float* __restrict__ aw,        // [B, S, S]
    float* __restrict__ attn_out)        // [B, H, S, S]
{
    __shared__ float sQ[AWARPS][64];     // 2 KB
    __shared__ float sP[AWARPS][1024];   // 32 KB
    __shared__ float sS[2112];           // 8.25 KB: K chunk [64][33] / V chunk [32][66]

    const int bid = blockIdx.x;          // 8192 blocks
    const int bh  = bid >> 7;            // 0..63
    const int qg  = bid & 127;
    const int b   = bh >> 3, h = bh & 7;
    const int w    = threadIdx.x >> 5;
    const int lane = threadIdx.x & 31;
    const int q    = qg * AWARPS + w;

    const float* Kt = g_kt + (size_t)bh * DEPTH * SEQ;
    const float* Vp = g_v  + (size_t)bh * SEQ * DEPTH;

    for (int i = threadIdx.x; i < AWARPS * 64; i += blockDim.x)
        sQ[i >> 6][i & 63] = g_q[((size_t)bh * SEQ + qg * AWARPS + (i >> 6)) * DEPTH + (i & 63)];
    __syncthreads();

    float qreg[64];
    #pragma unroll
    for (int d = 0; d < 64; d++) qreg[d] = sQ[w][d];

    // ---- Phase 1: scores (each lane owns k = 32*j + lane), track row max ----
    float m = -1e30f;
    for (int j = 0; j < 32; j++) {
        __syncthreads();
        for (int i = threadIdx.x; i < 64 * 32; i += blockDim.x) {
            int d = i >> 5, kk = i & 31;
            sS[d * 33 + kk] = Kt[(size_t)d * SEQ + j * 32 + kk];
        }
        __syncthreads();
        float s = 0.f;
        #pragma unroll
        for (int d = 0; d < 64; d++) s = fmaf(qreg[d], sS[d * 33 + lane], s);
        s *= 0.125f;                                    // 1/sqrt(64)
        s = fmaf(mask[b * SEQ + j * 32 + lane], -1e9f, s);
        sP[w][j * 32 + lane] = s;
        float cm = s;
        #pragma unroll
        for (int o = 16; o; o >>= 1) cm = fmaxf(cm, __shfl_xor_sync(0xffffffffu, cm, o));
        m = fmaxf(m, cm);
    }

    // ---- Phase 2: exp + row sum ----
    float lsum = 0.f;
    for (int j = 0; j < 32; j++) {
        float e = __expf(sP[w][j * 32 + lane] - m);
        sP[w][j * 32 + lane] = e;
        lsum += e;
    }
    #pragma unroll
    for (int o = 16; o; o >>= 1) lsum += __shfl_xor_sync(0xffffffffu, lsum, o);
    const float inv = 1.f / lsum;

    // ---- Phase 3: attn = p * additional_weights, write out, x = attn @ V ----
    float x0 = 0.f, x1 = 0.f;
    const int d0 = lane * 2;
    for (int j = 0; j < 32; j++) {
        __syncthreads();
        for (int i = threadIdx.x; i < 32 * 64; i += blockDim.x) {
            int kk = i >> 6, d = i & 63;
            sS[kk * 66 + d] = Vp[(size_t)(j * 32 + kk) * DEPTH + d];
        }
        __syncthreads();
        int k = j * 32 + lane;
        float p  = sP[w][k] * inv;
        float pa = p * aw[((size_t)(b * SEQ + q)) * SEQ + k];
        attn_out[((size_t)(bh * SEQ + q)) * SEQ + k] = pa;
        #pragma unroll
        for (int kk = 0; kk < 32; kk++) {
            float pp = __shfl_sync(0xffffffffu, pa, kk);
            float2 v2 = *(const float2*)&sS[kk * 66 + d0];
            x0 = fmaf(pp, v2.x, x0);
            x1 = fmaf(pp, v2.y, x1);
        }
    }
    float2 xo = make_float2(x0, x1);
    *(float2*)&g_x[((size_t)(b * SEQ + q)) * DM + h * DEPTH + d0] = xo;
}

// ---------------------------------------------------------------------------
extern "C" void kernel_launch(void* const* d_in, const int* in_sizes, int n_in,
                              void* d_out, int out_size)
{
    const float* q_in = (const float*)d_in[0];
    const float* k_in = (const float*)d_in[1];
    const float* v_in = (const float*)d_in[2];
    const float* mask = (const float*)d_in[3];
    const float* aw   = (const float*)d_in[4];
    const float* wq   = (const float*)d_in[5];
    const float* bq   = (const float*)d_in[6];
    const float* wk   = (const float*)d_in[7];
    const float* bk   = (const float*)d_in[8];
    const float* wv   = (const float*)d_in[9];
    const float* bv   = (const float*)d_in[10];
    const float* wo   = (const float*)d_in[11];
    const float* bo   = (const float*)d_in[12];

    float* out      = (float*)d_out;             // [8192, 512]
    float* attn_out = out + OUT_OFF;             // [8, 8, 1024, 1024]

    dim3 pgrid(DM / 128, MROWS / 128);           // (4, 64)

    proj_gemm<<<pgrid, 256>>>(q_in, wq, bq, nullptr, 0);   // Q -> g_q
    proj_gemm<<<pgrid, 256>>>(k_in, wk, bk, nullptr, 1);   // K -> g_kt (transposed)
    proj_gemm<<<pgrid, 256>>>(v_in, wv, bv, nullptr, 2);   // V -> g_v

    attn_kernel<<<BATCH * HEADS * (SEQ / AWARPS), 256>>>(mask, aw, attn_out);

    proj_gemm<<<pgrid, 256>>>(nullptr, wo, bo, out, 3);    // g_x (device) -> out
}

// round 6
// speedup vs baseline: 2.6604x; 2.6604x over previous
#include <cuda_runtime.h>
#include <math.h>

// Problem constants
#define BATCH 8
#define HEADS 8
#define SEQ   1024
#define DM    512
#define DEPTH 64
#define MROWS (BATCH*SEQ)          // 8192
#define OUT_OFF (BATCH*SEQ*DM)     // out region floats, then attn region

// Scratch (device globals; no runtime allocation allowed)
__device__ float g_q [BATCH*HEADS*SEQ*DEPTH];   // [bh][s][d]
__device__ float g_kt[BATCH*HEADS*DEPTH*SEQ];   // [bh][d][s]
__device__ float g_v [BATCH*HEADS*SEQ*DEPTH];   // [bh][s][d]
__device__ float g_x [BATCH*SEQ*DM];            // [b*s][h*64+d]

// ---------------------------------------------------------------------------
// Projection / output GEMM: C[8192,512] = X[8192,512] @ W[512,512] + bias
// mode 0 -> g_q; 1 -> g_kt (transposed); 2 -> g_v; 3 -> reads g_x, writes out
// ---------------------------------------------------------------------------
__global__ __launch_bounds__(256) void proj_gemm(
    const float* __restrict__ Xarg, const float* __restrict__ W,
    const float* __restrict__ bias, float* __restrict__ out, int mode)
{
    __shared__ float As[16][132];
    __shared__ float Bs[16][128];

    const float* X = (mode == 3) ? (const float*)g_x : Xarg;

    const int tid = threadIdx.x;
    const int tx = tid & 15, ty = tid >> 4;
    const int rowBase = blockIdx.y * 128;
    const int colBase = blockIdx.x * 128;

    float acc[8][8];
    #pragma unroll
    for (int i = 0; i < 8; i++)
        #pragma unroll
        for (int j = 0; j < 8; j++) acc[i][j] = 0.f;

    for (int k0 = 0; k0 < DM; k0 += 16) {
        #pragma unroll
        for (int i = 0; i < 2; i++) {
            int idx = tid * 2 + i;
            int r   = idx >> 2;
            int c4  = idx & 3;
            float4 v = *(const float4*)&X[(size_t)(rowBase + r) * DM + k0 + c4 * 4];
            As[c4*4+0][r] = v.x;
            As[c4*4+1][r] = v.y;
            As[c4*4+2][r] = v.z;
            As[c4*4+3][r] = v.w;
        }
        #pragma unroll
        for (int i = 0; i < 2; i++) {
            int idx = tid * 2 + i;
            int kk  = idx >> 5;
            int c4  = idx & 31;
            *(float4*)&Bs[kk][c4*4] =
                *(const float4*)&W[(size_t)(k0 + kk) * DM + colBase + c4 * 4];
        }
        __syncthreads();

        #pragma unroll
        for (int kk = 0; kk < 16; kk++) {
            float a[8], b[8];
            *(float4*)&a[0] = *(const float4*)&As[kk][ty*8];
            *(float4*)&a[4] = *(const float4*)&As[kk][ty*8+4];
            *(float4*)&b[0] = *(const float4*)&Bs[kk][tx*8];
            *(float4*)&b[4] = *(const float4*)&Bs[kk][tx*8+4];
            #pragma unroll
            for (int i = 0; i < 8; i++)
                #pragma unroll
                for (int j = 0; j < 8; j++)
                    acc[i][j] = fmaf(a[i], b[j], acc[i][j]);
        }
        __syncthreads();
    }

    #pragma unroll
    for (int i = 0; i < 8; i++) {
        int m  = rowBase + ty * 8 + i;
        int bb = m >> 10, s = m & 1023;
        #pragma unroll
        for (int j = 0; j < 8; j++) {
            int n = colBase + tx * 8 + j;
            float v = acc[i][j] + bias[n];
            int h = n >> 6, d = n & 63;
            int bh = bb * HEADS + h;
            if      (mode == 0) g_q [((size_t)bh * SEQ + s) * DEPTH + d] = v;
            else if (mode == 1) g_kt[((size_t)bh * DEPTH + d) * SEQ + s] = v;
            else if (mode == 2) g_v [((size_t)bh * SEQ + s) * DEPTH + d] = v;
            else                out[(size_t)m * DM + n] = v;
        }
    }
}

// ---------------------------------------------------------------------------
// score_gemm: S[bh][1024q][1024k] = (Q @ K^T) * 0.125 + mask*-1e9
// Written in-place into the attn output buffer. 128x128 tile, K-dim = 64.
// grid (8 ktiles, 8 qtiles, 64 bh), 256 threads, 8x8 microtile.
// ---------------------------------------------------------------------------
__global__ __launch_bounds__(256) void score_gemm(
    const float* __restrict__ mask,      // [B, S]
    float* __restrict__ attn)            // [bh, 1024, 1024]
{
    __shared__ float As[16][132];
    __shared__ float Bs[16][128];

    const int tid = threadIdx.x;
    const int tx = tid & 15, ty = tid >> 4;
    const int colBase = blockIdx.x * 128;     // k index
    const int rowBase = blockIdx.y * 128;     // q index
    const int bh = blockIdx.z;
    const int b  = bh >> 3;

    const float* Q  = g_q  + (size_t)bh * SEQ * DEPTH;   // [s][d]
    const float* Kt = g_kt + (size_t)bh * DEPTH * SEQ;   // [d][s]

    float acc[8][8];
    #pragma unroll
    for (int i = 0; i < 8; i++)
        #pragma unroll
        for (int j = 0; j < 8; j++) acc[i][j] = 0.f;

    for (int k0 = 0; k0 < DEPTH; k0 += 16) {
        // A tile: 128 q-rows x 16 d
        #pragma unroll
        for (int i = 0; i < 2; i++) {
            int idx = tid * 2 + i;
            int r   = idx >> 2;
            int c4  = idx & 3;
            float4 v = *(const float4*)&Q[(size_t)(rowBase + r) * DEPTH + k0 + c4 * 4];
            As[c4*4+0][r] = v.x;
            As[c4*4+1][r] = v.y;
            As[c4*4+2][r] = v.z;
            As[c4*4+3][r] = v.w;
        }
        // B tile: 16 d x 128 k
        #pragma unroll
        for (int i = 0; i < 2; i++) {
            int idx = tid * 2 + i;
            int kk  = idx >> 5;
            int c4  = idx & 31;
            *(float4*)&Bs[kk][c4*4] =
                *(const float4*)&Kt[(size_t)(k0 + kk) * SEQ + colBase + c4 * 4];
        }
        __syncthreads();

        #pragma unroll
        for (int kk = 0; kk < 16; kk++) {
            float a[8], bb[8];
            *(float4*)&a[0]  = *(const float4*)&As[kk][ty*8];
            *(float4*)&a[4]  = *(const float4*)&As[kk][ty*8+4];
            *(float4*)&bb[0] = *(const float4*)&Bs[kk][tx*8];
            *(float4*)&bb[4] = *(const float4*)&Bs[kk][tx*8+4];
            #pragma unroll
            for (int i = 0; i < 8; i++)
                #pragma unroll
                for (int j = 0; j < 8; j++)
                    acc[i][j] = fmaf(a[i], bb[j], acc[i][j]);
        }
        __syncthreads();
    }

    // Epilogue: scale + mask, vectorized store
    float msk[8];
    #pragma unroll
    for (int j = 0; j < 8; j++)
        msk[j] = -1e9f * mask[b * SEQ + colBase + tx * 8 + j];

    #pragma unroll
    for (int i = 0; i < 8; i++) {
        int q = rowBase + ty * 8 + i;
        float* dst = &attn[((size_t)bh * SEQ + q) * SEQ + colBase + tx * 8];
        float4 o0, o1;
        o0.x = fmaf(acc[i][0], 0.125f, msk[0]);
        o0.y = fmaf(acc[i][1], 0.125f, msk[1]);
        o0.z = fmaf(acc[i][2], 0.125f, msk[2]);
        o0.w = fmaf(acc[i][3], 0.125f, msk[3]);
        o1.x = fmaf(acc[i][4], 0.125f, msk[4]);
        o1.y = fmaf(acc[i][5], 0.125f, msk[5]);
        o1.z = fmaf(acc[i][6], 0.125f, msk[6]);
        o1.w = fmaf(acc[i][7], 0.125f, msk[7]);
        *(float4*)&dst[0] = o0;
        *(float4*)&dst[4] = o1;
    }
}

// ---------------------------------------------------------------------------
// softmax_aw: in-place row softmax over attn then multiply by aw.
// One block per row (bh*1024+q). 256 threads, 4 elems/thread.
// ---------------------------------------------------------------------------
__global__ __launch_bounds__(256) void softmax_aw(
    const float* __restrict__ aw,        // [B, S, S]
    float* __restrict__ attn)            // [bh, 1024, 1024]
{
    __shared__ float redm[8];
    __shared__ float reds[8];

    const int row = blockIdx.x;          // bh*1024 + q
    const int bh  = row >> 10, q = row & 1023;
    const int b   = bh >> 3;
    const int t    = threadIdx.x;
    const int wid  = t >> 5, lane = t & 31;

    float* p = attn + (size_t)row * SEQ;
    const float* awr = aw + ((size_t)(b * SEQ + q)) * SEQ;

    float v[4];
    #pragma unroll
    for (int i = 0; i < 4; i++) v[i] = p[t + i * 256];

    // block max
    float m = fmaxf(fmaxf(v[0], v[1]), fmaxf(v[2], v[3]));
    #pragma unroll
    for (int o = 16; o; o >>= 1) m = fmaxf(m, __shfl_xor_sync(0xffffffffu, m, o));
    if (lane == 0) redm[wid] = m;
    __syncthreads();
    float M = redm[0];
    #pragma unroll
    for (int i = 1; i < 8; i++) M = fmaxf(M, redm[i]);

    // exp + block sum
    float e[4], s = 0.f;
    #pragma unroll
    for (int i = 0; i < 4; i++) { e[i] = __expf(v[i] - M); s += e[i]; }
    #pragma unroll
    for (int o = 16; o; o >>= 1) s += __shfl_xor_sync(0xffffffffu, s, o);
    if (lane == 0) reds[wid] = s;
    __syncthreads();
    float S = 0.f;
    #pragma unroll
    for (int i = 0; i < 8; i++) S += reds[i];
    const float inv = 1.f / S;

    #pragma unroll
    for (int i = 0; i < 4; i++)
        p[t + i * 256] = e[i] * inv * awr[t + i * 256];
}

// ---------------------------------------------------------------------------
// pv_gemm: X[bh][1024q][64d] = attn[bh] @ V[bh].  128x64 tile, BK=32.
// grid (8 qtiles, 64 bh), 256 threads, 8x4 microtile. Writes g_x.
// ---------------------------------------------------------------------------
__global__ __launch_bounds__(256) void pv_gemm(const float* __restrict__ attn)
{
    __shared__ float As[32][132];   // [k][q-row]
    __shared__ float Bs[32][64];    // [k][d]

    const int tid = threadIdx.x;
    const int tx = tid & 15, ty = tid >> 4;
    const int rowBase = blockIdx.x * 128;     // q
    const int bh = blockIdx.y;
    const int b  = bh >> 3, h = bh & 7;

    const float* A = attn + (size_t)bh * SEQ * SEQ;     // [q][k]
    const float* V = g_v  + (size_t)bh * SEQ * DEPTH;   // [k][d]

    float acc[8][4];
    #pragma unroll
    for (int i = 0; i < 8; i++)
        #pragma unroll
        for (int j = 0; j < 4; j++) acc[i][j] = 0.f;

    for (int k0 = 0; k0 < SEQ; k0 += 32) {
        // A tile: 128 q-rows x 32 k  (1024 float4, 4 per thread)
        #pragma unroll
        for (int i = 0; i < 4; i++) {
            int idx = tid * 4 + i;            // 0..1023
            int r   = idx >> 3;               // 0..127
            int c4  = idx & 7;                // 0..7
            float4 v = *(const float4*)&A[(size_t)(rowBase + r) * SEQ + k0 + c4 * 4];
            As[c4*4+0][r] = v.x;
            As[c4*4+1][r] = v.y;
            As[c4*4+2][r] = v.z;
            As[c4*4+3][r] = v.w;
        }
        // B tile: 32 k x 64 d  (512 float4, 2 per thread)
        #pragma unroll
        for (int i = 0; i < 2; i++) {
            int idx = tid * 2 + i;            // 0..511
            int kk  = idx >> 4;               // 0..31
            int c4  = idx & 15;               // 0..15
            *(float4*)&Bs[kk][c4*4] =
                *(const float4*)&V[(size_t)(k0 + kk) * DEPTH + c4 * 4];
        }
        __syncthreads();

        #pragma unroll
        for (int kk = 0; kk < 32; kk++) {
            float a[8], bb[4];
            *(float4*)&a[0]  = *(const float4*)&As[kk][ty*8];
            *(float4*)&a[4]  = *(const float4*)&As[kk][ty*8+4];
            *(float4*)&bb[0] = *(const float4*)&Bs[kk][tx*4];
            #pragma unroll
            for (int i = 0; i < 8; i++)
                #pragma unroll
                for (int j = 0; j < 4; j++)
                    acc[i][j] = fmaf(a[i], bb[j], acc[i][j]);
        }
        __syncthreads();
    }

    #pragma unroll
    for (int i = 0; i < 8; i++) {
        int q = rowBase + ty * 8 + i;
        float4 o;
        o.x = acc[i][0]; o.y = acc[i][1]; o.z = acc[i][2]; o.w = acc[i][3];
        *(float4*)&g_x[((size_t)(b * SEQ + q)) * DM + h * DEPTH + tx * 4] = o;
    }
}

// ---------------------------------------------------------------------------
extern "C" void kernel_launch(void* const* d_in, const int* in_sizes, int n_in,
                              void* d_out, int out_size)
{
    const float* q_in = (const float*)d_in[0];
    const float* k_in = (const float*)d_in[1];
    const float* v_in = (const float*)d_in[2];
    const float* mask = (const float*)d_in[3];
    const float* aw   = (const float*)d_in[4];
    const float* wq   = (const float*)d_in[5];
    const float* bq   = (const float*)d_in[6];
    const float* wk   = (const float*)d_in[7];
    const float* bk   = (const float*)d_in[8];
    const float* wv   = (const float*)d_in[9];
    const float* bv   = (const float*)d_in[10];
    const float* wo   = (const float*)d_in[11];
    const float* bo   = (const float*)d_in[12];

    float* out      = (float*)d_out;             // [8192, 512]
    float* attn_out = out + OUT_OFF;             // [8, 8, 1024, 1024]

    dim3 pgrid(DM / 128, MROWS / 128);           // (4, 64)

    proj_gemm<<<pgrid, 256>>>(q_in, wq, bq, nullptr, 0);   // Q -> g_q
    proj_gemm<<<pgrid, 256>>>(k_in, wk, bk, nullptr, 1);   // K -> g_kt
    proj_gemm<<<pgrid, 256>>>(v_in, wv, bv, nullptr, 2);   // V -> g_v

    score_gemm<<<dim3(8, 8, 64), 256>>>(mask, attn_out);   // S in-place in attn
    softmax_aw<<<BATCH * HEADS * SEQ, 256>>>(aw, attn_out);// softmax * aw in-place
    pv_gemm<<<dim3(8, 64), 256>>>(attn_out);               // X -> g_x

    proj_gemm<<<pgrid, 256>>>(nullptr, wo, bo, out, 3);    // g_x -> out
}